// round 1
// baseline (speedup 1.0000x reference)
#include <cuda_runtime.h>
#include <cuda_bf16.h>
#include <cstdint>

// Shapes (compile-time; all powers of two):
// L=2, B=4, H=8, M=4096, D=128
// k_caches, v_caches : (L,B,H,M,D) f32
// latest_k, latest_v : (L,B,H,1,D) f32
// position_ids       : (B,1) int32
// seq_len            : scalar int
// out                : (2,L,B,H,M,D) f32  = stack([k_out, v_out])
//
// Semantics: out = stack(caches) with row (l,b,h,pos[b]) replaced by latest
// when pos[b] < seq_len.

#define D_SHIFT   7    // D   = 128
#define M_SHIFT   12   // M   = 4096
#define H_SHIFT   3    // H   = 8
#define B_SHIFT   2    // B   = 4
// float4 units per row of D: 128/4 = 32  -> 5 bits
#define D4_SHIFT  5
#define D4_MASK   31
#define M_MASK    4095
#define B_MASK    3

// floats per half (one cache tensor): L*B*H*M*D = 2*4*8*4096*128 = 2^25? no:
// 2*4*8 = 64 = 2^6; * 4096 = 2^18; *128 = 2^25 / wait: 2^6 * 2^12 * 2^7 = 2^25.
// Hmm: L*B*H = 64 = 2^6, M = 2^12, D = 2^7 -> 2^25 floats per half.
// float4s per half:
#define N4_HALF   (1 << 23)   // 2^25 floats / 4

__global__ __launch_bounds__(256)
void kv_update_kernel(const float4* __restrict__ kc,
                      const float4* __restrict__ vc,
                      const float4* __restrict__ lk,
                      const float4* __restrict__ lv,
                      const int*    __restrict__ pos,     // (B,1)
                      const int*    __restrict__ seq_len, // scalar
                      float4*       __restrict__ out)
{
    const unsigned i = blockIdx.x * blockDim.x + threadIdx.x;  // float4 idx over full out
    const bool isV = (i >= N4_HALF);
    const unsigned j = isV ? (i - N4_HALF) : i;                // float4 idx within half

    // Within half, layout is (L,B,H,M,D). In float4 units per row: 32.
    const unsigned m = (j >> D4_SHIFT) & M_MASK;
    const unsigned b = (j >> (D4_SHIFT + M_SHIFT + H_SHIFT)) & B_MASK;

    const int S = *seq_len;
    const int p = pos[b];

    float4 val;
    if ((int)m == p && (int)m < S) {
        // latest index (L,B,H,1,D): strip the m dimension
        const unsigned lj = ((j >> (D4_SHIFT + M_SHIFT)) << D4_SHIFT) | (j & D4_MASK);
        val = isV ? lv[lj] : lk[lj];
    } else {
        val = isV ? vc[j] : kc[j];
    }
    out[i] = val;
}

extern "C" void kernel_launch(void* const* d_in, const int* in_sizes, int n_in,
                              void* d_out, int out_size)
{
    const float4* kc  = (const float4*)d_in[0];
    const float4* vc  = (const float4*)d_in[1];
    const float4* lk  = (const float4*)d_in[2];
    const float4* lv  = (const float4*)d_in[3];
    const int*    pos = (const int*)   d_in[4];
    const int*    sl  = (const int*)   d_in[5];
    float4*       out = (float4*)      d_out;

    // total float4s = 2 * N4_HALF = 2^24 ; blocks = 2^24 / 256 = 65536
    const int threads = 256;
    const int blocks  = (2 * N4_HALF) / threads;
    kv_update_kernel<<<blocks, threads>>>(kc, vc, lk, lv, pos, sl, out);
}